// round 7
// baseline (speedup 1.0000x reference)
#include <cuda_runtime.h>

#define T_STEPS 10
#define B_SZ    32
#define CIN     3
#define COUT    64
#define SPAT    4096            // 64*64
#define N_THR   (T_STEPS * COUT)
#define DECAY   0.2f
#define INH     1.625f
#define KC      4.6166241f      /* 3.2 * log2(e) */

// Scratch: conv results for all timesteps, layout (t,b,c,h,w).
__device__ float    g_i[T_STEPS * B_SZ * COUT * SPAT];   // 335.5 MB
__device__ unsigned g_thr_keys[N_THR];
__device__ float4   g_thrv[N_THR];   // {thr, INH*thr, 8*log2e/thr, 0}

// ---------------------------------------------------------------------------
__global__ void init_keys() {
    int i = blockIdx.x * blockDim.x + threadIdx.x;
    if (i < N_THR) g_thr_keys[i] = 0u;   // key 0 == very negative float
}

// ---------------------------------------------------------------------------
// Conv 3x3, stride 1, pad 1 (R5 scalar version: proven at the FFMA floor).
// Each thread computes a 4-tall pixel column; per-(t,c) max via warp REDUX ->
// per-warp smem slot -> block reduce -> global atomic.
__global__ void __launch_bounds__(128) conv_kernel(const float* __restrict__ x,
                                                   const float* __restrict__ Wt) {
    __shared__ float    xs[CIN][18][34];     // 32x16 tile + halo
    __shared__ float    ws[COUT * 28];       // 27 weights + 1 pad per channel
    __shared__ unsigned swm[COUT][4];        // per-warp max keys

    const int tb  = blockIdx.z;              // t*B + b
    const int t   = tb >> 5;
    const int tid = threadIdx.y * 32 + threadIdx.x;
    const int wid = threadIdx.y;             // 4 warps

    for (int idx = tid; idx < COUT * 27; idx += 128) {
        int co = idx / 27;
        ws[co * 28 + (idx - co * 27)] = Wt[idx];
    }

    const float* xb = x + tb * (CIN * SPAT);
    const int y0 = blockIdx.y * 16;
    const int x0 = blockIdx.x * 32;
    for (int idx = tid; idx < CIN * 612; idx += 128) {
        int ci  = idx / 612;
        int rem = idx - ci * 612;
        int yy  = rem / 34;
        int xx  = rem - yy * 34;
        int gy = y0 + yy - 1, gx = x0 + xx - 1;
        float v = 0.f;
        if ((unsigned)gy < 64u && (unsigned)gx < 64u) v = xb[ci * SPAT + gy * 64 + gx];
        xs[ci][yy][xx] = v;
    }
    __syncthreads();

    const int px = threadIdx.x;
    const int py = threadIdx.y;              // 4 row-groups of 4
    float r[CIN][6][3];
#pragma unroll
    for (int ci = 0; ci < CIN; ci++)
#pragma unroll
        for (int rr = 0; rr < 6; rr++)
#pragma unroll
            for (int kx = 0; kx < 3; kx++)
                r[ci][rr][kx] = xs[ci][4 * py + rr][px + kx];

    float* out = g_i + tb * (COUT * SPAT) + (y0 + 4 * py) * 64 + x0 + px;

#pragma unroll 1
    for (int co = 0; co < COUT; co++) {
        float wl[28];
        float4* wlv = (float4*)wl;
        const float4* wv = (const float4*)(ws + co * 28);
#pragma unroll
        for (int q = 0; q < 7; q++) wlv[q] = wv[q];

        float accs[4];
#pragma unroll
        for (int ry = 0; ry < 4; ry++) {
            float a0 = 0.f, a1 = 0.f, a2 = 0.f;
#pragma unroll
            for (int ky = 0; ky < 3; ky++)
#pragma unroll
                for (int kx = 0; kx < 3; kx++) {
                    const int j = ky * 3 + kx;
                    a0 = fmaf(r[0][ry + ky][kx], wl[j],      a0);
                    a1 = fmaf(r[1][ry + ky][kx], wl[j + 9],  a1);
                    a2 = fmaf(r[2][ry + ky][kx], wl[j + 18], a2);
                }
            accs[ry] = (a0 + a1) + a2;
            out[co * SPAT + ry * 64] = accs[ry];
        }

        float mx = fmaxf(fmaxf(accs[0], accs[1]), fmaxf(accs[2], accs[3]));
        unsigned u   = __float_as_uint(mx);
        unsigned key = ((int)u < 0) ? ~u : (u | 0x80000000u);   // order-preserving
        key = __reduce_max_sync(0xffffffffu, key);
        if (px == 0) swm[co][wid] = key;
    }
    __syncthreads();
    if (tid < COUT) {
        unsigned m = swm[tid][0];
        m = max(m, swm[tid][1]); m = max(m, swm[tid][2]); m = max(m, swm[tid][3]);
        atomicMax(&g_thr_keys[t * COUT + tid], m);
    }
}

// ---------------------------------------------------------------------------
__global__ void finalize_thr() {
    int i = blockIdx.x * blockDim.x + threadIdx.x;
    if (i < N_THR) {
        unsigned k = g_thr_keys[i];
        unsigned u = (k & 0x80000000u) ? (k & 0x7FFFFFFFu) : ~k;
        float thr  = __uint_as_float(u) + 1e-4f;
        float zs   = 11.541560f / thr;        // 8*log2(e)/thr
        g_thrv[i]  = make_float4(thr, INH * thr, zs, 0.f);
    }
}

// ---------------------------------------------------------------------------
// LIF + ASF + WTA + inhibition. 64-pixel tiles, 2 pixels per warp, ONE
// barrier per timestep (stage-next-tile-before-barrier trick), fast sigmoid,
// winner-code spike reconstruction.
__global__ void __launch_bounds__(1024) lif_kernel(float* __restrict__ out) {
    __shared__ float  smi[2][COUT][65];  // i tiles, [channel][pixel] (65: odd stride)
    __shared__ int    swz[2][64];        // winner code per pixel
    __shared__ float4 sthr[N_THR];       // cached thresholds

    const int tx  = threadIdx.x;         // lane
    const int ty  = threadIdx.y;         // warp
    const int tid = ty * 32 + tx;
    const int b   = blockIdx.x >> 6;     // 64 tiles per batch image
    const int spb = (blockIdx.x & 63) * 64;

    if (tid < N_THR) sthr[tid] = g_thrv[tid];

    const int tstride = B_SZ * COUT * SPAT;
    const int r00 = (b * COUT + ty) * SPAT + spb + tx;   // ch ty, px tx
    const int RCH = 32 * SPAT;                            // +32 channels

    // prefetch t = 0, stage tile 0
    float l0 = g_i[r00];
    float l1 = g_i[r00 + 32];
    float l2 = g_i[r00 + RCH];
    float l3 = g_i[r00 + RCH + 32];
    smi[0][ty][tx]           = l0;
    smi[0][ty][tx + 32]      = l1;
    smi[0][ty + 32][tx]      = l2;
    smi[0][ty + 32][tx + 32] = l3;
    __syncthreads();
    l0 = g_i[r00 + tstride];
    l1 = g_i[r00 + tstride + 32];
    l2 = g_i[r00 + tstride + RCH];
    l3 = g_i[r00 + tstride + RCH + 32];

    // compute identity: warp ty owns pixels 2ty, 2ty+1; lane = channels tx, tx+32
    const int p0 = 2 * ty, p1 = 2 * ty + 1;
    float memA0 = 0.f, memA1 = 0.f;      // pixel p0, channels tx / tx+32
    float memB0 = 0.f, memB1 = 0.f;      // pixel p1

#pragma unroll
    for (int t = 0; t < T_STEPS; t++) {
        const int cur = t & 1, nxt = cur ^ 1;
        const float4 tv0 = sthr[t * COUT + tx];
        const float4 tv1 = sthr[t * COUT + tx + 32];

        int wz0, wz1;
#pragma unroll
        for (int pi = 0; pi < 2; pi++) {
            const int   p   = pi ? p1 : p0;
            float       m0  = pi ? memB0 : memA0;
            float       m1  = pi ? memB1 : memA1;
            const float i0  = smi[cur][tx][p];
            const float i1  = smi[cur][tx + 32][p];

            // fast ASF: thr / (1 + exp2(KC - cur*zs))
            float zn0 = fmaf(fmaxf(i0, 0.f), -tv0.z, KC);
            float zn1 = fmaf(fmaxf(i1, 0.f), -tv1.z, KC);
            float e0, e1, q0, q1;
            asm("ex2.approx.f32 %0, %1;" : "=f"(e0) : "f"(zn0));
            asm("ex2.approx.f32 %0, %1;" : "=f"(e1) : "f"(zn1));
            asm("rcp.approx.f32 %0, %1;" : "=f"(q0) : "f"(1.f + e0));
            asm("rcp.approx.f32 %0, %1;" : "=f"(q1) : "f"(1.f + e1));

            m0 = fmaf(m0, DECAY, tv0.x * q0);
            m1 = fmaf(m1, DECAY, tv1.x * q1);

            const int   s0i = m0 > tv0.x ? 1 : 0;
            const int   s1i = m1 > tv1.x ? 1 : 0;
            const float sc0 = s0i ? m0 : 0.f;
            const float sc1 = s1i ? m1 : 0.f;

            float bs; int bi;
            if (sc0 >= sc1) { bs = sc0; bi = (tx << 1) | s0i; }
            else            { bs = sc1; bi = ((tx + 32) << 1) | s1i; }

            unsigned ub   = __float_as_uint(bs);
            unsigned key  = ((int)ub < 0) ? ~ub : (ub | 0x80000000u);
            unsigned mk   = __reduce_max_sync(0xffffffffu, key);
            unsigned cand = (key == mk) ? (unsigned)bi : 0x7fffffffu;
            const int wz  = (int)__reduce_min_sync(0xffffffffu, cand);

            const int   wc  = wz >> 1;
            const float any = (float)(wz & 1);

            const float sn0 = (wc == tx)      ? (float)s0i : 0.f;
            const float sn1 = (wc == tx + 32) ? (float)s1i : 0.f;

            m0 = (sn0 > 0.f) ? 0.f : fmaf(-tv0.y, any, m0);
            m1 = (sn1 > 0.f) ? 0.f : fmaf(-tv1.y, any, m1);

            if (pi) { memB0 = m0; memB1 = m1; wz1 = wz; }
            else    { memA0 = m0; memA1 = m1; wz0 = wz; }
        }

        if (tx == 0) { swz[cur][p0] = wz0; swz[cur][p1] = wz1; }

        // stage t+1 tile into the other buffer BEFORE the barrier
        if (t + 1 < T_STEPS) {
            smi[nxt][ty][tx]           = l0;
            smi[nxt][ty][tx + 32]      = l1;
            smi[nxt][ty + 32][tx]      = l2;
            smi[nxt][ty + 32][tx + 32] = l3;
        }
        __syncthreads();

        // store phase: thread = (channel ty/ty+32, pixels tx/tx+32)
        const int ob = r00 + t * tstride;
        const int wa = swz[cur][tx];
        const int wb = swz[cur][tx + 32];
        out[ob]            = (wa == ((ty << 1) | 1))        ? 1.f : 0.f;
        out[ob + 32]       = (wb == ((ty << 1) | 1))        ? 1.f : 0.f;
        out[ob + RCH]      = (wa == (((ty + 32) << 1) | 1)) ? 1.f : 0.f;
        out[ob + RCH + 32] = (wb == (((ty + 32) << 1) | 1)) ? 1.f : 0.f;

        // prefetch t+2
        if (t + 2 < T_STEPS) {
            const int off = r00 + (t + 2) * tstride;
            l0 = g_i[off];
            l1 = g_i[off + 32];
            l2 = g_i[off + RCH];
            l3 = g_i[off + RCH + 32];
        }
    }
}

// ---------------------------------------------------------------------------
extern "C" void kernel_launch(void* const* d_in, const int* in_sizes, int n_in,
                              void* d_out, int out_size) {
    const float* x = (const float*)d_in[0];
    const float* W = (const float*)d_in[1];
    if (n_in >= 2 && in_sizes[0] == COUT * CIN * 9) {  // defensive order swap
        const float* tmp = x; x = W; W = tmp;
    }

    init_keys<<<1, N_THR>>>();

    dim3 cb(32, 4);
    dim3 cg(2, 4, T_STEPS * B_SZ);
    conv_kernel<<<cg, cb>>>(x, W);

    finalize_thr<<<1, N_THR>>>();

    lif_kernel<<<(B_SZ * SPAT) / 64, dim3(32, 32)>>>((float*)d_out);
}

// round 8
// speedup vs baseline: 1.1265x; 1.1265x over previous
#include <cuda_runtime.h>

#define T_STEPS 10
#define B_SZ    32
#define CIN     3
#define COUT    64
#define SPAT    4096            // 64*64
#define N_THR   (T_STEPS * COUT)
#define DECAY   0.2f
#define INH     1.625f
#define KC      4.6166241f      /* 3.2 * log2(e) */

// Scratch: conv results for all timesteps, layout (t,b,c,h,w).
__device__ float    g_i[T_STEPS * B_SZ * COUT * SPAT];   // 335.5 MB
__device__ unsigned g_thr_keys[N_THR];
__device__ float4   g_thrv[N_THR];   // {thr, INH*thr, 8*log2e/thr, 0}

// ---------------------------------------------------------------------------
__global__ void init_keys() {
    int i = blockIdx.x * blockDim.x + threadIdx.x;
    if (i < N_THR) g_thr_keys[i] = 0u;   // key 0 == very negative float
}

// ---------------------------------------------------------------------------
// Conv 3x3, stride 1, pad 1 (R5 scalar version: at the FFMA chip floor).
__global__ void __launch_bounds__(128) conv_kernel(const float* __restrict__ x,
                                                   const float* __restrict__ Wt) {
    __shared__ float    xs[CIN][18][34];     // 32x16 tile + halo
    __shared__ float    ws[COUT * 28];       // 27 weights + 1 pad per channel
    __shared__ unsigned swm[COUT][4];        // per-warp max keys

    const int tb  = blockIdx.z;              // t*B + b
    const int t   = tb >> 5;
    const int tid = threadIdx.y * 32 + threadIdx.x;
    const int wid = threadIdx.y;             // 4 warps

    for (int idx = tid; idx < COUT * 27; idx += 128) {
        int co = idx / 27;
        ws[co * 28 + (idx - co * 27)] = Wt[idx];
    }

    const float* xb = x + tb * (CIN * SPAT);
    const int y0 = blockIdx.y * 16;
    const int x0 = blockIdx.x * 32;
    for (int idx = tid; idx < CIN * 612; idx += 128) {
        int ci  = idx / 612;
        int rem = idx - ci * 612;
        int yy  = rem / 34;
        int xx  = rem - yy * 34;
        int gy = y0 + yy - 1, gx = x0 + xx - 1;
        float v = 0.f;
        if ((unsigned)gy < 64u && (unsigned)gx < 64u) v = xb[ci * SPAT + gy * 64 + gx];
        xs[ci][yy][xx] = v;
    }
    __syncthreads();

    const int px = threadIdx.x;
    const int py = threadIdx.y;              // 4 row-groups of 4
    float r[CIN][6][3];
#pragma unroll
    for (int ci = 0; ci < CIN; ci++)
#pragma unroll
        for (int rr = 0; rr < 6; rr++)
#pragma unroll
            for (int kx = 0; kx < 3; kx++)
                r[ci][rr][kx] = xs[ci][4 * py + rr][px + kx];

    float* out = g_i + tb * (COUT * SPAT) + (y0 + 4 * py) * 64 + x0 + px;

#pragma unroll 1
    for (int co = 0; co < COUT; co++) {
        float wl[28];
        float4* wlv = (float4*)wl;
        const float4* wv = (const float4*)(ws + co * 28);
#pragma unroll
        for (int q = 0; q < 7; q++) wlv[q] = wv[q];

        float accs[4];
#pragma unroll
        for (int ry = 0; ry < 4; ry++) {
            float a0 = 0.f, a1 = 0.f, a2 = 0.f;
#pragma unroll
            for (int ky = 0; ky < 3; ky++)
#pragma unroll
                for (int kx = 0; kx < 3; kx++) {
                    const int j = ky * 3 + kx;
                    a0 = fmaf(r[0][ry + ky][kx], wl[j],      a0);
                    a1 = fmaf(r[1][ry + ky][kx], wl[j + 9],  a1);
                    a2 = fmaf(r[2][ry + ky][kx], wl[j + 18], a2);
                }
            accs[ry] = (a0 + a1) + a2;
            out[co * SPAT + ry * 64] = accs[ry];
        }

        float mx = fmaxf(fmaxf(accs[0], accs[1]), fmaxf(accs[2], accs[3]));
        unsigned u   = __float_as_uint(mx);
        unsigned key = ((int)u < 0) ? ~u : (u | 0x80000000u);   // order-preserving
        key = __reduce_max_sync(0xffffffffu, key);
        if (px == 0) swm[co][wid] = key;
    }
    __syncthreads();
    if (tid < COUT) {
        unsigned m = swm[tid][0];
        m = max(m, swm[tid][1]); m = max(m, swm[tid][2]); m = max(m, swm[tid][3]);
        atomicMax(&g_thr_keys[t * COUT + tid], m);
    }
}

// ---------------------------------------------------------------------------
__global__ void finalize_thr() {
    int i = blockIdx.x * blockDim.x + threadIdx.x;
    if (i < N_THR) {
        unsigned k = g_thr_keys[i];
        unsigned u = (k & 0x80000000u) ? (k & 0x7FFFFFFFu) : ~k;
        float thr  = __uint_as_float(u) + 1e-4f;
        float zs   = 11.541560f / thr;        // 8*log2(e)/thr
        g_thrv[i]  = make_float4(thr, INH * thr, zs, 0.f);
    }
}

// ---------------------------------------------------------------------------
// LIF + ASF + WTA + inhibition. R5 structure (32-px tile, 2 ch/thread,
// regs capped for 2 blocks/SM) with ONE barrier per timestep: compute ->
// winner write -> stage next tile -> bar -> store -> prefetch t+2.
__global__ void __launch_bounds__(1024, 2) lif_kernel(float* __restrict__ out) {
    __shared__ float  smi[2][COUT][33];  // i tiles, [channel][pixel]
    __shared__ int    swz[2][32];        // winner code per pixel
    __shared__ float4 sthr[N_THR];       // cached thresholds

    const int tx  = threadIdx.x;         // lane
    const int ty  = threadIdx.y;         // warp
    const int tid = ty * 32 + tx;
    const int b   = blockIdx.x >> 7;     // 128 tiles per batch image
    const int spb = (blockIdx.x & 127) * 32;

    for (int i = tid; i < N_THR; i += 1024) sthr[i] = g_thrv[i];

    const int tstride = B_SZ * COUT * SPAT;
    const int row0    = (b * COUT + ty) * SPAT + spb + tx;
    const int row1    = row0 + 32 * SPAT;

    // t = 0: load + stage, then prefetch t = 1
    float l0 = g_i[row0];
    float l1 = g_i[row1];
    smi[0][ty][tx]      = l0;
    smi[0][ty + 32][tx] = l1;
    __syncthreads();
    l0 = g_i[row0 + tstride];
    l1 = g_i[row1 + tstride];

    float mem0 = 0.f, mem1 = 0.f;

#pragma unroll
    for (int t = 0; t < T_STEPS; t++) {
        const int cur = t & 1, nxt = cur ^ 1;

        // ---- compute phase: x = channel, pixel = ty ----
        const float  i0  = smi[cur][tx][ty];
        const float  i1  = smi[cur][tx + 32][ty];
        const float4 tv0 = sthr[t * COUT + tx];
        const float4 tv1 = sthr[t * COUT + tx + 32];

        // fast ASF: thr / (1 + exp2(KC - cur*zs))
        float zn0 = fmaf(fmaxf(i0, 0.f), -tv0.z, KC);
        float zn1 = fmaf(fmaxf(i1, 0.f), -tv1.z, KC);
        float e0, e1, q0, q1;
        asm("ex2.approx.f32 %0, %1;" : "=f"(e0) : "f"(zn0));
        asm("ex2.approx.f32 %0, %1;" : "=f"(e1) : "f"(zn1));
        asm("rcp.approx.f32 %0, %1;" : "=f"(q0) : "f"(1.f + e0));
        asm("rcp.approx.f32 %0, %1;" : "=f"(q1) : "f"(1.f + e1));

        mem0 = fmaf(mem0, DECAY, tv0.x * q0);
        mem1 = fmaf(mem1, DECAY, tv1.x * q1);

        const int   s0i = mem0 > tv0.x ? 1 : 0;
        const int   s1i = mem1 > tv1.x ? 1 : 0;
        const float sc0 = s0i ? mem0 : 0.f;
        const float sc1 = s1i ? mem1 : 0.f;

        // per-lane candidate; lower channel wins ties (argmax-first semantics)
        float bs; int bi;
        if (sc0 >= sc1) { bs = sc0; bi = (tx << 1) | s0i; }
        else            { bs = sc1; bi = ((tx + 32) << 1) | s1i; }

        unsigned ub   = __float_as_uint(bs);
        unsigned key  = ((int)ub < 0) ? ~ub : (ub | 0x80000000u);
        unsigned mk   = __reduce_max_sync(0xffffffffu, key);
        unsigned cand = (key == mk) ? (unsigned)bi : 0x7fffffffu;
        const int wz  = (int)__reduce_min_sync(0xffffffffu, cand);

        const int   wc  = wz >> 1;
        const float any = (float)(wz & 1);            // winner's spike -> any_sp

        const float sn0 = (wc == tx)      ? (float)s0i : 0.f;
        const float sn1 = (wc == tx + 32) ? (float)s1i : 0.f;

        mem0 = (sn0 > 0.f) ? 0.f : fmaf(-tv0.y, any, mem0);
        mem1 = (sn1 > 0.f) ? 0.f : fmaf(-tv1.y, any, mem1);

        if (tx == 0) swz[cur][ty] = wz;  // one word per pixel

        // ---- stage t+1 tile into the other buffer BEFORE the barrier ----
        if (t + 1 < T_STEPS) {
            smi[nxt][ty][tx]      = l0;
            smi[nxt][ty + 32][tx] = l1;
        }
        __syncthreads();                 // the only barrier this timestep

        // ---- store phase: x = pixel (coalesced); reconstruct spikes ----
        const int wzp = swz[cur][tx];
        out[row0 + t * tstride] = (wzp == ((ty << 1) | 1))        ? 1.f : 0.f;
        out[row1 + t * tstride] = (wzp == (((ty + 32) << 1) | 1)) ? 1.f : 0.f;

        // ---- prefetch t+2 (covered by next iteration's compute) ----
        if (t + 2 < T_STEPS) {
            l0 = g_i[row0 + (t + 2) * tstride];
            l1 = g_i[row1 + (t + 2) * tstride];
        }
    }
}

// ---------------------------------------------------------------------------
extern "C" void kernel_launch(void* const* d_in, const int* in_sizes, int n_in,
                              void* d_out, int out_size) {
    const float* x = (const float*)d_in[0];
    const float* W = (const float*)d_in[1];
    if (n_in >= 2 && in_sizes[0] == COUT * CIN * 9) {  // defensive order swap
        const float* tmp = x; x = W; W = tmp;
    }

    init_keys<<<1, N_THR>>>();

    dim3 cb(32, 4);
    dim3 cg(2, 4, T_STEPS * B_SZ);
    conv_kernel<<<cg, cb>>>(x, W);

    finalize_thr<<<1, N_THR>>>();

    lif_kernel<<<(B_SZ * SPAT) / 32, dim3(32, 32)>>>((float*)d_out);
}

// round 9
// speedup vs baseline: 1.2098x; 1.0739x over previous
#include <cuda_runtime.h>

#define T_STEPS 10
#define B_SZ    32
#define CIN     3
#define COUT    64
#define SPAT    4096            // 64*64
#define N_THR   (T_STEPS * COUT)
#define DECAY   0.2f
#define INH     1.625f
#define KC      4.6166241f      /* 3.2 * log2(e) */

// Scratch: conv results, CHANNEL-LAST layout (t, b, sp, c).  335.5 MB
__device__ float    g_i[T_STEPS * B_SZ * SPAT * COUT];
__device__ unsigned g_thr_keys[N_THR];
__device__ float4   g_thrv[N_THR];   // {thr, INH*thr, 8*log2e/thr, 0}

// ---------------------------------------------------------------------------
__global__ void init_keys() {
    int i = blockIdx.x * blockDim.x + threadIdx.x;
    if (i < N_THR) g_thr_keys[i] = 0u;   // key 0 == very negative float
}

// ---------------------------------------------------------------------------
// Conv 3x3, stride 1, pad 1 (R5 math, bit-identical accumulation) writing
// CHANNEL-LAST output. Results are staged in smem in 8-channel chunks so the
// global stores stay 100% sector-efficient.
__global__ void __launch_bounds__(128) conv_kernel(const float* __restrict__ x,
                                                   const float* __restrict__ Wt) {
    __shared__ float    xs[CIN][18][34];     // 32x16 tile + halo
    __shared__ float    ws[COUT * 28];       // 27 weights + 1 pad per channel
    __shared__ unsigned swm[COUT][4];        // per-warp max keys
    __shared__ float    stage[512][9];       // [local sp][chunk channel], pad 9

    const int tb  = blockIdx.z;              // t*B + b
    const int t   = tb >> 5;
    const int tid = threadIdx.y * 32 + threadIdx.x;
    const int wid = threadIdx.y;             // 4 warps

    for (int idx = tid; idx < COUT * 27; idx += 128) {
        int co = idx / 27;
        ws[co * 28 + (idx - co * 27)] = Wt[idx];
    }

    const float* xb = x + tb * (CIN * SPAT);
    const int y0 = blockIdx.y * 16;
    const int x0 = blockIdx.x * 32;
    for (int idx = tid; idx < CIN * 612; idx += 128) {
        int ci  = idx / 612;
        int rem = idx - ci * 612;
        int yy  = rem / 34;
        int xx  = rem - yy * 34;
        int gy = y0 + yy - 1, gx = x0 + xx - 1;
        float v = 0.f;
        if ((unsigned)gy < 64u && (unsigned)gx < 64u) v = xb[ci * SPAT + gy * 64 + gx];
        xs[ci][yy][xx] = v;
    }
    __syncthreads();

    const int px = threadIdx.x;
    const int py = threadIdx.y;              // 4 row-groups of 4
    float r[CIN][6][3];
#pragma unroll
    for (int ci = 0; ci < CIN; ci++)
#pragma unroll
        for (int rr = 0; rr < 6; rr++)
#pragma unroll
            for (int kx = 0; kx < 3; kx++)
                r[ci][rr][kx] = xs[ci][4 * py + rr][px + kx];

    const int tbbase = tb * (SPAT * COUT);   // element base for this (t,b)

#pragma unroll 1
    for (int chunk = 0; chunk < 8; chunk++) {
#pragma unroll 1
        for (int coi = 0; coi < 8; coi++) {
            const int co = chunk * 8 + coi;
            float wl[28];
            float4* wlv = (float4*)wl;
            const float4* wv = (const float4*)(ws + co * 28);
#pragma unroll
            for (int q = 0; q < 7; q++) wlv[q] = wv[q];

            float accs[4];
#pragma unroll
            for (int ry = 0; ry < 4; ry++) {
                float a0 = 0.f, a1 = 0.f, a2 = 0.f;
#pragma unroll
                for (int ky = 0; ky < 3; ky++)
#pragma unroll
                    for (int kx = 0; kx < 3; kx++) {
                        const int j = ky * 3 + kx;
                        a0 = fmaf(r[0][ry + ky][kx], wl[j],      a0);
                        a1 = fmaf(r[1][ry + ky][kx], wl[j + 9],  a1);
                        a2 = fmaf(r[2][ry + ky][kx], wl[j + 18], a2);
                    }
                accs[ry] = (a0 + a1) + a2;
                stage[(4 * py + ry) * 32 + px][coi] = accs[ry];
            }

            float mx = fmaxf(fmaxf(accs[0], accs[1]), fmaxf(accs[2], accs[3]));
            unsigned u   = __float_as_uint(mx);
            unsigned key = ((int)u < 0) ? ~u : (u | 0x80000000u);
            key = __reduce_max_sync(0xffffffffu, key);
            if (px == 0) swm[co][wid] = key;
        }
        __syncthreads();
        // flush 512 positions x 8 channels, channel-last, fully coalesced
#pragma unroll
        for (int i = 0; i < 32; i++) {
            int flat = i * 128 + tid;
            int pos  = flat >> 3;
            int coi  = flat & 7;
            int row  = pos >> 5, col = pos & 31;
            int sp   = (y0 + row) * 64 + x0 + col;
            g_i[tbbase + sp * COUT + chunk * 8 + coi] = stage[pos][coi];
        }
        __syncthreads();
    }

    if (tid < COUT) {
        unsigned m = swm[tid][0];
        m = max(m, swm[tid][1]); m = max(m, swm[tid][2]); m = max(m, swm[tid][3]);
        atomicMax(&g_thr_keys[t * COUT + tid], m);
    }
}

// ---------------------------------------------------------------------------
__global__ void finalize_thr() {
    int i = blockIdx.x * blockDim.x + threadIdx.x;
    if (i < N_THR) {
        unsigned k = g_thr_keys[i];
        unsigned u = (k & 0x80000000u) ? (k & 0x7FFFFFFFu) : ~k;
        float thr  = __uint_as_float(u) + 1e-4f;
        float zs   = 11.541560f / thr;        // 8*log2(e)/thr
        g_thrv[i]  = make_float4(thr, INH * thr, zs, 0.f);
    }
}

// ---------------------------------------------------------------------------
// LIF + ASF + WTA + inhibition. WARP-PER-PIXEL on channel-last data:
// lane owns channels 2tx, 2tx+1 (one coalesced float2 load per t), WTA via
// 2 REDUX ops, mem in 2 regs. NO barriers, NO smem tiles in the t-loop.
// Winner codes buffered; one barrier; coalesced spike-store phase at the end.
__global__ void __launch_bounds__(1024) lif_kernel(float* __restrict__ out) {
    __shared__ float2 sth[320], sih[320], szs[320];  // [t*32 + pair]
    __shared__ int    swz[32][11];                   // [pixel][t], pad 11

    const int tx  = threadIdx.x;         // lane -> channel pair
    const int ty  = threadIdx.y;         // warp -> pixel
    const int tid = ty * 32 + tx;
    const int b   = blockIdx.x >> 7;     // 128 blocks per batch image
    const int spb = (blockIdx.x & 127) * 32;

    if (tid < 320) {
        int t = tid >> 5, p = tid & 31;
        float4 a = g_thrv[t * COUT + 2 * p];
        float4 c = g_thrv[t * COUT + 2 * p + 1];
        sth[tid] = make_float2(a.x, c.x);
        sih[tid] = make_float2(a.y, c.y);
        szs[tid] = make_float2(a.z, c.z);
    }
    __syncthreads();

    const int sp    = spb + ty;
    const int c0    = 2 * tx, c1 = 2 * tx + 1;
    const float2* ip = (const float2*)g_i;
    const int pbase = (b * SPAT + sp) * 32 + tx;     // float2 index
    const int tstep = B_SZ * SPAT * 32;              // float2 per timestep

    float2 b0 = ip[pbase];
    float2 b1 = ip[pbase + tstep];
    float m0 = 0.f, m1 = 0.f;

#pragma unroll
    for (int t = 0; t < T_STEPS; t++) {
        const float2 iv = (t & 1) ? b1 : b0;
        if (t + 2 < T_STEPS) {                       // depth-2 prefetch
            if (t & 1) b1 = ip[pbase + (t + 2) * tstep];
            else       b0 = ip[pbase + (t + 2) * tstep];
        }
        const float2 th = sth[t * 32 + tx];
        const float2 ih = sih[t * 32 + tx];
        const float2 zs = szs[t * 32 + tx];

        // fast ASF: thr / (1 + exp2(KC - cur*zs))
        float zn0 = fmaf(fmaxf(iv.x, 0.f), -zs.x, KC);
        float zn1 = fmaf(fmaxf(iv.y, 0.f), -zs.y, KC);
        float e0, e1, q0, q1;
        asm("ex2.approx.f32 %0, %1;" : "=f"(e0) : "f"(zn0));
        asm("ex2.approx.f32 %0, %1;" : "=f"(e1) : "f"(zn1));
        asm("rcp.approx.f32 %0, %1;" : "=f"(q0) : "f"(1.f + e0));
        asm("rcp.approx.f32 %0, %1;" : "=f"(q1) : "f"(1.f + e1));

        m0 = fmaf(m0, DECAY, th.x * q0);
        m1 = fmaf(m1, DECAY, th.y * q1);

        const int   s0i = m0 > th.x ? 1 : 0;
        const int   s1i = m1 > th.y ? 1 : 0;
        const float sc0 = s0i ? m0 : 0.f;
        const float sc1 = s1i ? m1 : 0.f;

        // per-lane candidate; lower channel wins ties (argmax-first semantics)
        float bs; int bi;
        if (sc0 >= sc1) { bs = sc0; bi = (c0 << 1) | s0i; }
        else            { bs = sc1; bi = (c1 << 1) | s1i; }

        unsigned ub   = __float_as_uint(bs);
        unsigned key  = ((int)ub < 0) ? ~ub : (ub | 0x80000000u);
        unsigned mk   = __reduce_max_sync(0xffffffffu, key);
        unsigned cand = (key == mk) ? (unsigned)bi : 0x7fffffffu;
        const int wz  = (int)__reduce_min_sync(0xffffffffu, cand);

        const int   wc  = wz >> 1;
        const float any = (float)(wz & 1);            // winner's spike -> any_sp

        const float sn0 = (wc == c0) ? (float)s0i : 0.f;
        const float sn1 = (wc == c1) ? (float)s1i : 0.f;

        m0 = (sn0 > 0.f) ? 0.f : fmaf(-ih.x, any, m0);
        m1 = (sn1 > 0.f) ? 0.f : fmaf(-ih.y, any, m1);

        if (tx == 0) swz[ty][t] = wz;
    }
    __syncthreads();

    // store phase: reference layout (t,b,c,h,w); lanes = pixels (coalesced)
    const int obase = (b * COUT) * SPAT + spb + tx;
    const int ostep = B_SZ * COUT * SPAT;
#pragma unroll
    for (int t = 0; t < T_STEPS; t++) {
        const int w = swz[tx][t];
        out[obase + t * ostep + ty * SPAT]        = (w == ((ty << 1) | 1))        ? 1.f : 0.f;
        out[obase + t * ostep + (ty + 32) * SPAT] = (w == (((ty + 32) << 1) | 1)) ? 1.f : 0.f;
    }
}

// ---------------------------------------------------------------------------
extern "C" void kernel_launch(void* const* d_in, const int* in_sizes, int n_in,
                              void* d_out, int out_size) {
    const float* x = (const float*)d_in[0];
    const float* W = (const float*)d_in[1];
    if (n_in >= 2 && in_sizes[0] == COUT * CIN * 9) {  // defensive order swap
        const float* tmp = x; x = W; W = tmp;
    }

    init_keys<<<1, N_THR>>>();

    dim3 cb(32, 4);
    dim3 cg(2, 4, T_STEPS * B_SZ);
    conv_kernel<<<cg, cb>>>(x, W);

    finalize_thr<<<1, N_THR>>>();

    lif_kernel<<<(B_SZ * SPAT) / 32, dim3(32, 32)>>>((float*)d_out);
}

// round 10
// speedup vs baseline: 1.3938x; 1.1521x over previous
#include <cuda_runtime.h>

#define T_STEPS 10
#define B_SZ    32
#define CIN     3
#define COUT    64
#define SPAT    4096            // 64*64
#define N_THR   (T_STEPS * COUT)
#define DECAY   0.2f
#define INH     1.625f
#define KC      4.6166241f      /* 3.2 * log2(e) */

// Scratch: conv results, CHANNEL-LAST layout (t, b, sp, c).  335.5 MB
__device__ float    g_i[T_STEPS * B_SZ * SPAT * COUT];
__device__ unsigned g_thr_keys[N_THR];
__device__ float4   g_thrv[N_THR];   // {thr, INH*thr, 8*log2e/thr, 0}

// ---------------------------------------------------------------------------
__global__ void init_keys() {
    int i = blockIdx.x * blockDim.x + threadIdx.x;
    if (i < N_THR) g_thr_keys[i] = 0u;   // key 0 == very negative float
}

// ---------------------------------------------------------------------------
// Conv 3x3, stride 1, pad 1. LANE = CHANNEL-PAIR: lane tx owns channels
// 2tx/2tx+1 with all 54 weights in registers; the warp walks positions with a
// register-resident sliding 3x3x3 input window (broadcast LDS). Stores are
// float2 per lane -> natively coalesced channel-last, NO staging.
// Per-channel FMA order identical to R5 (a0/a1/a2 per ci, ky-major).

// One column-step: compute col C_ with slot mapping kx->(S0_,S1_,S2_),
// store, update max, optionally slide window (load col C_+3 into slot S0_).
#define STEP(S0_, S1_, S2_, C_, DOLOAD_) do {                                 \
    float a0 = 0.f, a1 = 0.f, a2 = 0.f, b0 = 0.f, b1 = 0.f, b2 = 0.f;         \
    const int SL_[3] = {S0_, S1_, S2_};                                       \
    _Pragma("unroll")                                                         \
    for (int ky = 0; ky < 3; ky++)                                            \
        _Pragma("unroll")                                                     \
        for (int kx = 0; kx < 3; kx++) {                                      \
            const int j = ky * 3 + kx;                                        \
            const int s = SL_[kx];                                            \
            a0 = fmaf(xw[0][s][ky], w0[j],      a0);                          \
            a1 = fmaf(xw[1][s][ky], w0[j + 9],  a1);                          \
            a2 = fmaf(xw[2][s][ky], w0[j + 18], a2);                          \
            b0 = fmaf(xw[0][s][ky], w1[j],      b0);                          \
            b1 = fmaf(xw[1][s][ky], w1[j + 9],  b1);                          \
            b2 = fmaf(xw[2][s][ky], w1[j + 18], b2);                          \
        }                                                                     \
    const float v0 = (a0 + a1) + a2;                                          \
    const float v1 = (b0 + b1) + b2;                                          \
    gp[sprow + (C_) * 32 + tx] = make_float2(v0, v1);                         \
    mx0 = fmaxf(mx0, v0);                                                     \
    mx1 = fmaxf(mx1, v1);                                                     \
    if (DOLOAD_) {                                                            \
        _Pragma("unroll")                                                     \
        for (int ci = 0; ci < CIN; ci++)                                      \
            _Pragma("unroll")                                                 \
            for (int ky = 0; ky < 3; ky++)                                    \
                xw[ci][S0_][ky] = xs[ci][row + ky][(C_) + 3];                 \
    }                                                                         \
} while (0)

__global__ void __launch_bounds__(128) conv_kernel(const float* __restrict__ x,
                                                   const float* __restrict__ Wt) {
    __shared__ float    xs[CIN][18][34];     // 32x16 tile + halo
    __shared__ float    ws[COUT * 28];       // 27 weights + 1 pad per channel
    __shared__ unsigned smax[COUT][4];       // per-warp max keys

    const int tb  = blockIdx.z;              // t*B + b
    const int t   = tb >> 5;
    const int tx  = threadIdx.x;             // lane -> channels 2tx, 2tx+1
    const int wid = threadIdx.y;             // 4 warps -> 4 row groups
    const int tid = wid * 32 + tx;

    for (int idx = tid; idx < COUT * 27; idx += 128) {
        int co = idx / 27;
        ws[co * 28 + (idx - co * 27)] = Wt[idx];
    }

    const float* xb = x + tb * (CIN * SPAT);
    const int y0 = blockIdx.y * 16;
    const int x0 = blockIdx.x * 32;
    for (int idx = tid; idx < CIN * 612; idx += 128) {
        int ci  = idx / 612;
        int rem = idx - ci * 612;
        int yy  = rem / 34;
        int xx  = rem - yy * 34;
        int gy = y0 + yy - 1, gx = x0 + xx - 1;
        float v = 0.f;
        if ((unsigned)gy < 64u && (unsigned)gx < 64u) v = xb[ci * SPAT + gy * 64 + gx];
        xs[ci][yy][xx] = v;
    }
    __syncthreads();

    // 54 weights -> registers (one-time)
    float w0[28], w1[28];
    {
        const float4* p0 = (const float4*)(ws + (2 * tx) * 28);
        const float4* p1 = (const float4*)(ws + (2 * tx + 1) * 28);
#pragma unroll
        for (int q = 0; q < 7; q++) {
            float4 a = p0[q];
            w0[4 * q] = a.x; w0[4 * q + 1] = a.y; w0[4 * q + 2] = a.z; w0[4 * q + 3] = a.w;
            float4 c = p1[q];
            w1[4 * q] = c.x; w1[4 * q + 1] = c.y; w1[4 * q + 2] = c.z; w1[4 * q + 3] = c.w;
        }
    }

    float2* gp = (float2*)g_i + (long)tb * (SPAT * 32);
    float mx0 = -1e30f, mx1 = -1e30f;

#pragma unroll 1
    for (int rr = 0; rr < 4; rr++) {
        const int row = 4 * wid + rr;                       // tile row 0..15
        const int sprow = ((y0 + row) * 64 + x0) * 32;      // float2 base

        // prime window: xs cols 0,1,2 -> slots 0,1,2
        float xw[CIN][3][3];                                // [ci][slot][ky]
#pragma unroll
        for (int ci = 0; ci < CIN; ci++)
#pragma unroll
            for (int s = 0; s < 3; s++)
#pragma unroll
                for (int ky = 0; ky < 3; ky++)
                    xw[ci][s][ky] = xs[ci][row + ky][s];

#pragma unroll 1
        for (int c3 = 0; c3 < 30; c3 += 3) {
            STEP(0, 1, 2, c3 + 0, true);
            STEP(1, 2, 0, c3 + 1, true);
            STEP(2, 0, 1, c3 + 2, true);
        }
        STEP(0, 1, 2, 30, true);     // loads col 33 into slot 0
        STEP(1, 2, 0, 31, false);
    }

    // per-(t,c) max: order-preserving keys, block reduce, one global atomic
    unsigned u0 = __float_as_uint(mx0);
    unsigned k0 = ((int)u0 < 0) ? ~u0 : (u0 | 0x80000000u);
    unsigned u1 = __float_as_uint(mx1);
    unsigned k1 = ((int)u1 < 0) ? ~u1 : (u1 | 0x80000000u);
    smax[2 * tx][wid]     = k0;
    smax[2 * tx + 1][wid] = k1;
    __syncthreads();
    if (tid < COUT) {
        unsigned m = smax[tid][0];
        m = max(m, smax[tid][1]); m = max(m, smax[tid][2]); m = max(m, smax[tid][3]);
        atomicMax(&g_thr_keys[t * COUT + tid], m);
    }
}

// ---------------------------------------------------------------------------
__global__ void finalize_thr() {
    int i = blockIdx.x * blockDim.x + threadIdx.x;
    if (i < N_THR) {
        unsigned k = g_thr_keys[i];
        unsigned u = (k & 0x80000000u) ? (k & 0x7FFFFFFFu) : ~k;
        float thr  = __uint_as_float(u) + 1e-4f;
        float zs   = 11.541560f / thr;        // 8*log2(e)/thr
        g_thrv[i]  = make_float4(thr, INH * thr, zs, 0.f);
    }
}

// ---------------------------------------------------------------------------
// LIF + ASF + WTA + inhibition (R9, proven): warp-per-pixel on channel-last
// data, lane owns channels 2tx/2tx+1 (one coalesced float2 load per t), WTA
// via 2 REDUX ops, mem in regs. No barriers/smem tiles in the t-loop.
__global__ void __launch_bounds__(1024) lif_kernel(float* __restrict__ out) {
    __shared__ float2 sth[320], sih[320], szs[320];  // [t*32 + pair]
    __shared__ int    swz[32][11];                   // [pixel][t], pad 11

    const int tx  = threadIdx.x;         // lane -> channel pair
    const int ty  = threadIdx.y;         // warp -> pixel
    const int tid = ty * 32 + tx;
    const int b   = blockIdx.x >> 7;     // 128 blocks per batch image
    const int spb = (blockIdx.x & 127) * 32;

    if (tid < 320) {
        int t = tid >> 5, p = tid & 31;
        float4 a = g_thrv[t * COUT + 2 * p];
        float4 c = g_thrv[t * COUT + 2 * p + 1];
        sth[tid] = make_float2(a.x, c.x);
        sih[tid] = make_float2(a.y, c.y);
        szs[tid] = make_float2(a.z, c.z);
    }
    __syncthreads();

    const int sp    = spb + ty;
    const int c0    = 2 * tx, c1 = 2 * tx + 1;
    const float2* ip = (const float2*)g_i;
    const int pbase = (b * SPAT + sp) * 32 + tx;     // float2 index
    const int tstep = B_SZ * SPAT * 32;              // float2 per timestep

    float2 b0 = ip[pbase];
    float2 b1 = ip[pbase + tstep];
    float m0 = 0.f, m1 = 0.f;

#pragma unroll
    for (int t = 0; t < T_STEPS; t++) {
        const float2 iv = (t & 1) ? b1 : b0;
        if (t + 2 < T_STEPS) {                       // depth-2 prefetch
            if (t & 1) b1 = ip[pbase + (t + 2) * tstep];
            else       b0 = ip[pbase + (t + 2) * tstep];
        }
        const float2 th = sth[t * 32 + tx];
        const float2 ih = sih[t * 32 + tx];
        const float2 zs = szs[t * 32 + tx];

        // fast ASF: thr / (1 + exp2(KC - cur*zs))
        float zn0 = fmaf(fmaxf(iv.x, 0.f), -zs.x, KC);
        float zn1 = fmaf(fmaxf(iv.y, 0.f), -zs.y, KC);
        float e0, e1, q0, q1;
        asm("ex2.approx.f32 %0, %1;" : "=f"(e0) : "f"(zn0));
        asm("ex2.approx.f32 %0, %1;" : "=f"(e1) : "f"(zn1));
        asm("rcp.approx.f32 %0, %1;" : "=f"(q0) : "f"(1.f + e0));
        asm("rcp.approx.f32 %0, %1;" : "=f"(q1) : "f"(1.f + e1));

        m0 = fmaf(m0, DECAY, th.x * q0);
        m1 = fmaf(m1, DECAY, th.y * q1);

        const int   s0i = m0 > th.x ? 1 : 0;
        const int   s1i = m1 > th.y ? 1 : 0;
        const float sc0 = s0i ? m0 : 0.f;
        const float sc1 = s1i ? m1 : 0.f;

        // per-lane candidate; lower channel wins ties (argmax-first semantics)
        float bs; int bi;
        if (sc0 >= sc1) { bs = sc0; bi = (c0 << 1) | s0i; }
        else            { bs = sc1; bi = (c1 << 1) | s1i; }

        unsigned ub   = __float_as_uint(bs);
        unsigned key  = ((int)ub < 0) ? ~ub : (ub | 0x80000000u);
        unsigned mk   = __reduce_max_sync(0xffffffffu, key);
        unsigned cand = (key == mk) ? (unsigned)bi : 0x7fffffffu;
        const int wz  = (int)__reduce_min_sync(0xffffffffu, cand);

        const int   wc  = wz >> 1;
        const float any = (float)(wz & 1);            // winner's spike -> any_sp

        const float sn0 = (wc == c0) ? (float)s0i : 0.f;
        const float sn1 = (wc == c1) ? (float)s1i : 0.f;

        m0 = (sn0 > 0.f) ? 0.f : fmaf(-ih.x, any, m0);
        m1 = (sn1 > 0.f) ? 0.f : fmaf(-ih.y, any, m1);

        if (tx == 0) swz[ty][t] = wz;
    }
    __syncthreads();

    // store phase: reference layout (t,b,c,h,w); lanes = pixels (coalesced)
    const int obase = (b * COUT) * SPAT + spb + tx;
    const int ostep = B_SZ * COUT * SPAT;
#pragma unroll
    for (int t = 0; t < T_STEPS; t++) {
        const int w = swz[tx][t];
        out[obase + t * ostep + ty * SPAT]        = (w == ((ty << 1) | 1))        ? 1.f : 0.f;
        out[obase + t * ostep + (ty + 32) * SPAT] = (w == (((ty + 32) << 1) | 1)) ? 1.f : 0.f;
    }
}

// ---------------------------------------------------------------------------
extern "C" void kernel_launch(void* const* d_in, const int* in_sizes, int n_in,
                              void* d_out, int out_size) {
    const float* x = (const float*)d_in[0];
    const float* W = (const float*)d_in[1];
    if (n_in >= 2 && in_sizes[0] == COUT * CIN * 9) {  // defensive order swap
        const float* tmp = x; x = W; W = tmp;
    }

    init_keys<<<1, N_THR>>>();

    dim3 cb(32, 4);
    dim3 cg(2, 4, T_STEPS * B_SZ);
    conv_kernel<<<cg, cb>>>(x, W);

    finalize_thr<<<1, N_THR>>>();

    lif_kernel<<<(B_SZ * SPAT) / 32, dim3(32, 32)>>>((float*)d_out);
}